// round 17
// baseline (speedup 1.0000x reference)
#include <cuda_runtime.h>
#include <cuda_bf16.h>
#include <stdint.h>

// LUT_82085414961764: out = a[idx]*d + b[idx], idx = searchsorted(x, d, 'left')
// R16: R15's fused two-state table scaled to NB=7680 (dynamic smem, 72 KB/CTA,
// 3 CTAs/SM) to cut the data-weighted tagged fraction ~48%->~29%, plus batch-8
// stage-structured ILP (R10-proven at 3 CTAs) to hold L1 utilization.
//   empty  : e = (a[lo], b[lo])              -> 1 LDS.64, FMA, done
//   tagged : e.x = 0x7F800000|lo, e.y = x_s[lo]
//            idx = lo; if (e.y < d) { ++idx; while (x_s[idx] < d) ++idx; }
//            then gather ab_s[idx].
// Bin function t = fmaf(v, scale, shift): monotone (scale>=0), IDENTICAL at
// build & query, so lo is a provably correct lower bound. Tag (exp==255)
// cannot collide with finite a.

#define KMAX 1024
#define NB   7680

// dynamic smem layout (bytes): fused[NB] f2 | x_s[KMAX+2] f | ab_s[KMAX+1] f2
#define FUSED_BYTES (NB * 8)
#define XS_BYTES    ((KMAX + 2) * 4)          // +2 keeps ab_s 8B-aligned
#define AB_BYTES    ((KMAX + 1) * 8)
#define SMEM_BYTES  (FUSED_BYTES + XS_BYTES + AB_BYTES)   // 73744 B

__global__ __launch_bounds__(512, 3)
void lut_kernel(const float* __restrict__ data,
                const float* __restrict__ x,
                const float* __restrict__ a,
                const float* __restrict__ b,
                float* __restrict__ out,
                int K, unsigned n)
{
    extern __shared__ char smem[];
    float2* fused = (float2*)smem;
    float*  x_s   = (float*)(smem + FUSED_BYTES);
    float2* ab_s  = (float2*)(smem + FUSED_BYTES + XS_BYTES);

    const int tid = threadIdx.x;
    const int bd  = blockDim.x;

    // ---- build phase ----------------------------------------------------
    for (int i = tid; i < K; i += bd)  x_s[i] = x[i];
    for (int i = tid; i <= K; i += bd) ab_s[i] = make_float2(a[i], b[i]);
    if (tid == 0) x_s[K] = __int_as_float(0x7F800000);  // +inf sentinel
    __syncthreads();

    const float LO    = x_s[0];
    const float span  = x_s[K - 1] - LO;
    const float scale = (span > 0.0f) ? ((float)NB / span) : 0.0f;
    const float shift = -LO * scale;
    const float NBf   = (float)NB;

    // monotone bin function — identical expression at build and query
    auto g = [&](float v) -> int {
        float t = fmaf(v, scale, shift);
        if (t < 0.0f) return 0;
        if (t >= NBf) return NB - 1;
        return (int)t;
    };

    for (int bin = tid; bin < NB; bin += bd) {
        int lo = 0, hi = K;
        while (lo < hi) {
            int mid = (lo + hi) >> 1;
            if (g(x_s[mid]) < bin) lo = mid + 1; else hi = mid;
        }
        float2 e;
        if (lo < K && g(x_s[lo]) == bin) {
            e.x = __uint_as_float(0x7F800000u | (unsigned)lo);  // tagged
            e.y = x_s[lo];                  // first breakpoint of this bin
        } else {
            e = ab_s[lo];                   // empty: direct coefficients
        }
        fused[bin] = e;
    }
    __syncthreads();

    // single-element path (tails)
    auto lut1 = [&](float d) -> float {
        float t = fmaf(d, scale, shift);
        int bin;
        if (t < 0.0f)      bin = 0;
        else if (t >= NBf) bin = NB - 1;
        else               bin = (int)t;
        float2 e = fused[bin];
        unsigned ux = __float_as_uint(e.x);
        if ((ux & 0x7F800000u) == 0x7F800000u) {
            int idx = (int)(ux & 0x7FFu);
            if (e.y < d) {                     // register compare (free)
                ++idx;
                while (x_s[idx] < d) ++idx;    // sentinel-terminated
            }
            e = ab_s[idx];
        }
        return fmaf(e.x, d, e.y);
    };

    const unsigned n4 = n >> 2;
    const float4* __restrict__ in4  = (const float4*)data;
    float4* __restrict__       out4 = (float4*)out;
    const unsigned stride = (unsigned)gridDim.x * (unsigned)bd;
    const unsigned step2  = stride * 2u;

    unsigned i = (unsigned)blockIdx.x * (unsigned)bd + (unsigned)tid;

    // ---- main loop: 8 elements/thread/iter, stage-structured for ILP ----
    for (; i + stride < n4; i += step2) {
        float4 v0 = in4[i];
        float4 v1 = in4[i + stride];
        float dv[8] = {v0.x, v0.y, v0.z, v0.w, v1.x, v1.y, v1.z, v1.w};
        float2 ev[8];

        // stage 1: bins + fused loads (8 independent LDS.64)
        #pragma unroll
        for (int j = 0; j < 8; ++j) {
            float t = fmaf(dv[j], scale, shift);
            int bin;
            if (t < 0.0f)      bin = 0;
            else if (t >= NBf) bin = NB - 1;
            else               bin = (int)t;
            ev[j] = fused[bin];
        }

        // stage 2: tagged lanes resolve index (first compare from register)
        #pragma unroll
        for (int j = 0; j < 8; ++j) {
            unsigned ux = __float_as_uint(ev[j].x);
            if ((ux & 0x7F800000u) == 0x7F800000u) {
                int idx = (int)(ux & 0x7FFu);
                if (ev[j].y < dv[j]) {             // free first compare
                    ++idx;
                    while (x_s[idx] < dv[j]) ++idx;
                }
                ev[j] = ab_s[idx];
            }
        }

        // stage 3: FMA + stores
        out4[i] = make_float4(fmaf(ev[0].x, dv[0], ev[0].y),
                              fmaf(ev[1].x, dv[1], ev[1].y),
                              fmaf(ev[2].x, dv[2], ev[2].y),
                              fmaf(ev[3].x, dv[3], ev[3].y));
        out4[i + stride] = make_float4(fmaf(ev[4].x, dv[4], ev[4].y),
                                       fmaf(ev[5].x, dv[5], ev[5].y),
                                       fmaf(ev[6].x, dv[6], ev[6].y),
                                       fmaf(ev[7].x, dv[7], ev[7].y));
    }

    // leftover single float4
    for (; i < n4; i += stride) {
        float4 v = in4[i];
        float4 r;
        r.x = lut1(v.x);
        r.y = lut1(v.y);
        r.z = lut1(v.z);
        r.w = lut1(v.w);
        out4[i] = r;
    }

    // scalar tail (n not divisible by 4)
    for (unsigned k = (n4 << 2) + (unsigned)blockIdx.x * (unsigned)bd + (unsigned)tid;
         k < n; k += stride) {
        out[k] = lut1(data[k]);
    }
}

extern "C" void kernel_launch(void* const* d_in, const int* in_sizes, int n_in,
                              void* d_out, int out_size)
{
    const float* data = (const float*)d_in[0];
    const float* x    = (const float*)d_in[1];
    const float* a    = (const float*)d_in[2];
    const float* b    = (const float*)d_in[3];
    float* out        = (float*)d_out;

    int K = in_sizes[1];
    if (K > KMAX) K = KMAX;  // problem constant is 1024
    unsigned n = (unsigned)out_size;

    cudaFuncSetAttribute(lut_kernel,
                         cudaFuncAttributeMaxDynamicSharedMemorySize,
                         SMEM_BYTES);

    const int threads = 512;
    int blocks = 456;  // 3 CTAs per SM on 152 SMs
    long long need = ((long long)n / 4 + threads - 1) / threads;
    if ((long long)blocks > need && need > 0) blocks = (int)need;
    if (blocks < 1) blocks = 1;

    lut_kernel<<<blocks, threads, SMEM_BYTES>>>(data, x, a, b, out, K, n);
}